// round 12
// baseline (speedup 1.0000x reference)
#include <cuda_runtime.h>
#include <math.h>

// Problem constants
#define BATCH      8192
#define PIECES     32
#define NNZ        (BATCH * PIECES)      // 262144
#define NFEAT      768
#define FTOUT      512
#define NSLICE     8
#define SCOLS      64                    // FTOUT / NSLICE
#define WSTRIDE    68                    // padded smem row stride (floats): conflict-free gathers
#define ROWS_ITER  32                    // batch rows per iteration
#define ITERS_TOT  (BATCH / ROWS_ITER)   // 256
#define BLOCKS_X   19                    // 19 * 8 slices = 152 blocks = #SMs
#define THREADS    512
#define IDX4STRIDE 33                    // staging stride in int4 units

// shared memory layout
#define OFF_W       0                    // float index
#define OFF_IDX4    13056                // int4 index (= 52224 floats / 4)
#define SM_BYTES    ((OFF_IDX4 + ROWS_ITER * IDX4STRIDE) * 16)   // 225792 B <= 227KB cap

// Self-cleaning scratch (zero-initialized at module load; each launch returns it to zero).
__device__ float        g_acc[BATCH];
__device__ unsigned int g_cnt[BATCH];

__device__ __forceinline__ float sat01(float x) { return __saturatef(x); }

__device__ __forceinline__ void ffma2(unsigned long long& acc, unsigned long long w,
                                      unsigned long long vv) {
    asm("fma.rn.f32x2 %0, %1, %2, %3;" : "=l"(acc) : "l"(w), "l"(vv), "l"(acc));
}
__device__ __forceinline__ unsigned long long packf2(float lo, float hi) {
    unsigned long long r;
    asm("mov.b64 %0, {%1, %2};" : "=l"(r) : "f"(lo), "f"(hi));
    return r;
}
__device__ __forceinline__ void unpackf2(float& lo, float& hi, unsigned long long v) {
    asm("mov.b64 {%0, %1}, %2;" : "=f"(lo), "=f"(hi) : "l"(v));
}

__global__ __launch_bounds__(THREADS, 1)
void ft_kernel(const int* __restrict__ stm_idx,     // [2, NNZ] int32; features at +NNZ
               const int* __restrict__ nstm_idx,
               const float* __restrict__ values,    // [NNZ]
               const float* __restrict__ ft_w,      // [768, 512]
               const float* __restrict__ ft_b,      // [512]
               const float* __restrict__ out_w,     // [1024, 1]
               const float* __restrict__ out_b,     // [1]
               float* __restrict__ out)             // [BATCH]
{
    extern __shared__ float sm[];
    int4* smi4 = (int4*)sm;

    const int tid = threadIdx.x;
    const int s   = blockIdx.y;          // column slice 0..7

    // ---- Load ft_w column slice [768 x 64] into smem (stride-68 rows) ----
    for (int i = tid; i < NFEAT * (SCOLS / 4); i += THREADS) {
        const int f  = i >> 4;
        const int c4 = i & 15;
        const float4 w = *(const float4*)(ft_w + f * FTOUT + s * SCOLS + c4 * 4);
        *(float4*)(sm + OFF_W + f * WSTRIDE + c4 * 4) = w;
    }

    // ---- Per-thread constants ----
    const int q  = tid & 15;             // float4-group within slice
    const int rl = tid >> 4;             // local row 0..31
    const int q4 = q * 4;
    const float4 ftb = *(const float4*)(ft_b + s * SCOLS + q4);
    const float4 owS = *(const float4*)(out_w + s * SCOLS + q4);
    const float4 owN = *(const float4*)(out_w + FTOUT + s * SCOLS + q4);
    const float  ob  = out_b[0];
    const unsigned long long b01 = packf2(ftb.x, ftb.y);
    const unsigned long long b23 = packf2(ftb.z, ftb.w);

    // ---- Staging prefetch (registers) for the first iteration ----
    const bool stager = (tid < (ROWS_ITER * PIECES) / 4);   // tid < 256
    int4 pa = make_int4(0,0,0,0), pb = make_int4(0,0,0,0);
    float4 pv = make_float4(0.f,0.f,0.f,0.f);
    int it = blockIdx.x;
    if (stager) {
        const int n0 = it * ROWS_ITER * PIECES;
        pa = *(const int4*)(stm_idx  + NNZ + n0 + tid * 4);
        pb = *(const int4*)(nstm_idx + NNZ + n0 + tid * 4);
        pv = *(const float4*)(values + n0 + tid * 4);
    }
    __syncthreads();

    // ---- Persistent loop over row-iterations ----
    while (it < ITERS_TOT) {
        // Store prefetched entries: (fS*68, fN*68, value_bits, 0) per piece.
        if (stager) {
            const int row = tid >> 3;
            const int d   = OFF_IDX4 + row * IDX4STRIDE + (tid & 7) * 4;
            smi4[d + 0] = make_int4(pa.x * WSTRIDE, pb.x * WSTRIDE, __float_as_int(pv.x), 0);
            smi4[d + 1] = make_int4(pa.y * WSTRIDE, pb.y * WSTRIDE, __float_as_int(pv.y), 0);
            smi4[d + 2] = make_int4(pa.z * WSTRIDE, pb.z * WSTRIDE, __float_as_int(pv.z), 0);
            smi4[d + 3] = make_int4(pa.w * WSTRIDE, pb.w * WSTRIDE, __float_as_int(pv.w), 0);
        }
        __syncthreads();

        const int rbase = it * ROWS_ITER;
        const int itn = it + BLOCKS_X;

        // Prefetch next iteration's staging data (latency overlapped with compute below).
        if (stager && itn < ITERS_TOT) {
            const int n0 = itn * ROWS_ITER * PIECES;
            pa = *(const int4*)(stm_idx  + NNZ + n0 + tid * 4);
            pb = *(const int4*)(nstm_idx + NNZ + n0 + tid * 4);
            pv = *(const float4*)(values + n0 + tid * 4);
        }

        // ---- Accumulate this thread's 4 columns for one batch row ----
        unsigned long long aS01 = b01, aS23 = b23, aN01 = b01, aN23 = b23;
        const int4* eptr = smi4 + OFF_IDX4 + rl * IDX4STRIDE;
        #pragma unroll
        for (int p = 0; p < PIECES; p++) {
            const int4 e = eptr[p];      // one broadcast LDS.128 per piece
            unsigned long long vv;
            asm("mov.b64 %0, {%1, %1};" : "=l"(vv) : "r"(e.z));
            const ulonglong2 wS = *(const ulonglong2*)(sm + e.x + q4);
            const ulonglong2 wN = *(const ulonglong2*)(sm + e.y + q4);
            ffma2(aS01, wS.x, vv);
            ffma2(aS23, wS.y, vv);
            ffma2(aN01, wN.x, vv);
            ffma2(aN23, wN.y, vv);
        }

        // clip(0,1) then dot with out_w slice
        float sx, sy, sz, sw, nx, ny, nz, nw;
        unpackf2(sx, sy, aS01); unpackf2(sz, sw, aS23);
        unpackf2(nx, ny, aN01); unpackf2(nz, nw, aN23);
        float partial =
            sat01(sx) * owS.x + sat01(sy) * owS.y +
            sat01(sz) * owS.z + sat01(sw) * owS.w +
            sat01(nx) * owN.x + sat01(ny) * owN.y +
            sat01(nz) * owN.z + sat01(nw) * owN.w;

        // reduce across the 16 lanes covering this row's 64 columns
        #pragma unroll
        for (int off = 8; off > 0; off >>= 1)
            partial += __shfl_xor_sync(0xffffffffu, partial, off, 16);

        // ---- Fused output: 8th slice to arrive finishes the row ----
        if (q == 0) {
            const int row = rbase + rl;
            atomicAdd(&g_acc[row], partial);
            __threadfence();
            const unsigned prev = atomicAdd(&g_cnt[row], 1u);
            if (prev == NSLICE - 1) {
                const float total = atomicAdd(&g_acc[row], 0.0f);  // forced L2 read
                out[row] = 1.0f / (1.0f + __expf(-(total + ob)));
                g_acc[row] = 0.0f;      // self-clean for next launch/replay
                g_cnt[row] = 0u;
            }
        }

        __syncthreads();   // protect staging buffers before next store
        it = itn;
    }
}

extern "C" void kernel_launch(void* const* d_in, const int* in_sizes, int n_in,
                              void* d_out, int out_size)
{
    (void)in_sizes; (void)n_in; (void)out_size;
    const int*   stm_idx  = (const int*)  d_in[0];  // [2, NNZ] int32
    const int*   nstm_idx = (const int*)  d_in[1];  // [2, NNZ] int32
    const float* values   = (const float*)d_in[2];  // [NNZ]
    const float* ft_w     = (const float*)d_in[3];  // [768, 512]
    const float* ft_b     = (const float*)d_in[4];  // [512]
    const float* out_w    = (const float*)d_in[5];  // [1024, 1]
    const float* out_b    = (const float*)d_in[6];  // [1]
    float* out = (float*)d_out;

    cudaFuncSetAttribute(ft_kernel, cudaFuncAttributeMaxDynamicSharedMemorySize, SM_BYTES);

    dim3 grid(BLOCKS_X, NSLICE);
    ft_kernel<<<grid, THREADS, SM_BYTES>>>(stm_idx, nstm_idx, values, ft_w, ft_b,
                                           out_w, out_b, out);
}

// round 17
// speedup vs baseline: 1.7617x; 1.7617x over previous
#include <cuda_runtime.h>
#include <math.h>

// Problem constants
#define BATCH      8192
#define PIECES     32
#define NNZ        (BATCH * PIECES)      // 262144
#define NFEAT      768
#define FTOUT      512
#define NSLICE     16
#define SCOLS      32                    // FTOUT / NSLICE
#define ROWS_ITER  64                    // batch rows per iteration
#define ITERS_TOT  (BATCH / ROWS_ITER)   // 128
#define BLOCKS_X   19                    // 19 * 16 slices = 304 CTAs = 2 per SM
#define THREADS    512

// shared memory layout (in 4-byte words)
// [0, 24576)          weight slice 768 x 32 f32, XOR-swizzled within each row
// [24576, 28928)      staging: 64 rows x 34 int2 (32 entries + 1 int2 pad, int4-aligned rows)
#define W_WORDS     (NFEAT * SCOLS)      // 24576
#define E2_BASE     (W_WORDS / 2)        // 12288 (int2 units)
#define E2_STRIDE   34                   // int2 per staged row (even -> int4 aligned)
#define SM_WORDS    (W_WORDS + ROWS_ITER * E2_STRIDE * 2)   // 28928
#define SM_BYTES    (SM_WORDS * 4)       // 115712 B; x2 CTAs = 231424 <= 228KB/SM

// Deterministic scratch, transposed [batch][slice]: one writer per element, no atomics.
__device__ float g_partial[BATCH * NSLICE];

__device__ __forceinline__ float sat01(float x) { return __saturatef(x); }

__device__ __forceinline__ void ffma2(unsigned long long& acc, unsigned long long w,
                                      unsigned long long vv) {
    asm("fma.rn.f32x2 %0, %1, %2, %3;" : "=l"(acc) : "l"(w), "l"(vv), "l"(acc));
}
__device__ __forceinline__ unsigned long long packf2(float lo, float hi) {
    unsigned long long r;
    asm("mov.b64 %0, {%1, %2};" : "=l"(r) : "f"(lo), "f"(hi));
    return r;
}
__device__ __forceinline__ void unpackf2(float& lo, float& hi, unsigned long long v) {
    asm("mov.b64 {%0, %1}, %2;" : "=f"(lo), "=f"(hi) : "l"(v));
}

__global__ __launch_bounds__(THREADS, 2)
void ft_kernel(const int* __restrict__ stm_idx,     // [2, NNZ] int32; features at +NNZ
               const int* __restrict__ nstm_idx,
               const float* __restrict__ values,    // [NNZ]
               const float* __restrict__ ft_w,      // [768, 512]
               const float* __restrict__ ft_b,      // [512]
               const float* __restrict__ out_w)     // [1024, 1]
{
    extern __shared__ float sm[];
    int4* smi4 = (int4*)sm;
    const int2* sme2 = (const int2*)sm;

    const int tid = threadIdx.x;
    const int s   = blockIdx.y;          // column slice 0..15

    // ---- Load ft_w column slice [768 x 32] into smem, XOR-swizzled per row ----
    // word addr = f*32 + ((c4 ^ (f & 7)) << 2): gather phases hit all 32 banks.
    for (int i = tid; i < NFEAT * (SCOLS / 4); i += THREADS) {
        const int f  = i >> 3;           // feature row
        const int c4 = i & 7;            // float4 group within slice
        const float4 w = *(const float4*)(ft_w + f * FTOUT + s * SCOLS + c4 * 4);
        *(float4*)(sm + f * SCOLS + ((c4 ^ (f & 7)) << 2)) = w;
    }

    // ---- Per-thread constants ----
    const int q  = tid & 7;              // float4-group within slice (cols q*4..q*4+3)
    const int rl = tid >> 3;             // local row 0..63
    const int q4 = q * 4;
    const float4 ftb = *(const float4*)(ft_b + s * SCOLS + q4);
    const float4 owS = *(const float4*)(out_w + s * SCOLS + q4);
    const float4 owN = *(const float4*)(out_w + FTOUT + s * SCOLS + q4);
    const unsigned long long b01 = packf2(ftb.x, ftb.y);
    const unsigned long long b23 = packf2(ftb.z, ftb.w);

    // ---- Staging prefetch (registers) for the first iteration; all threads stage ----
    int4 pa, pb; float4 pv;
    int it = blockIdx.x;
    {
        const int n0 = it * ROWS_ITER * PIECES;
        pa = *(const int4*)(stm_idx  + NNZ + n0 + tid * 4);
        pb = *(const int4*)(nstm_idx + NNZ + n0 + tid * 4);
        pv = *(const float4*)(values + n0 + tid * 4);
    }
    __syncthreads();

    // ---- Persistent loop over row-iterations ----
    while (it < ITERS_TOT) {
        // Store staged entries: per piece int2 { fS*32 | fN*32<<16, value_bits }.
        {
            const int row = tid >> 3;            // 0..63
            const int g   = tid & 7;             // 8 int4-pairs per row
            const int d4  = (E2_BASE >> 1) + row * (E2_STRIDE >> 1) + g * 2;
            smi4[d4 + 0] = make_int4((pa.x * SCOLS) | ((pb.x * SCOLS) << 16), __float_as_int(pv.x),
                                     (pa.y * SCOLS) | ((pb.y * SCOLS) << 16), __float_as_int(pv.y));
            smi4[d4 + 1] = make_int4((pa.z * SCOLS) | ((pb.z * SCOLS) << 16), __float_as_int(pv.z),
                                     (pa.w * SCOLS) | ((pb.w * SCOLS) << 16), __float_as_int(pv.w));
        }
        __syncthreads();

        const int rbase = it * ROWS_ITER;
        const int itn = it + BLOCKS_X;

        // Prefetch next iteration's staging data (overlapped with gather loop below).
        if (itn < ITERS_TOT) {
            const int n0 = itn * ROWS_ITER * PIECES;
            pa = *(const int4*)(stm_idx  + NNZ + n0 + tid * 4);
            pb = *(const int4*)(nstm_idx + NNZ + n0 + tid * 4);
            pv = *(const float4*)(values + n0 + tid * 4);
        }

        // ---- Accumulate this thread's 4 columns for one batch row ----
        unsigned long long aS01 = b01, aS23 = b23, aN01 = b01, aN23 = b23;
        const int2* eptr = sme2 + E2_BASE + rl * E2_STRIDE;
        #pragma unroll
        for (int p = 0; p < PIECES; p++) {
            const int2 e = eptr[p];              // broadcast LDS.64 (4 rows/warp, no conflicts)
            const int fS = e.x & 0xffff;         // f*32
            const int fN = ((unsigned)e.x) >> 16;
            unsigned long long vv;
            asm("mov.b64 %0, {%1, %1};" : "=l"(vv) : "r"(e.y));
            const ulonglong2 wS = *(const ulonglong2*)(sm + fS + (((q ^ (fS >> 5)) & 7) << 2));
            const ulonglong2 wN = *(const ulonglong2*)(sm + fN + (((q ^ (fN >> 5)) & 7) << 2));
            ffma2(aS01, wS.x, vv);
            ffma2(aS23, wS.y, vv);
            ffma2(aN01, wN.x, vv);
            ffma2(aN23, wN.y, vv);
        }

        // clip(0,1) then dot with out_w slice
        float sx, sy, sz, sw, nx, ny, nz, nw;
        unpackf2(sx, sy, aS01); unpackf2(sz, sw, aS23);
        unpackf2(nx, ny, aN01); unpackf2(nz, nw, aN23);
        float partial =
            sat01(sx) * owS.x + sat01(sy) * owS.y +
            sat01(sz) * owS.z + sat01(sw) * owS.w +
            sat01(nx) * owN.x + sat01(ny) * owN.y +
            sat01(nz) * owN.z + sat01(nw) * owN.w;

        // reduce across the 8 lanes covering this row's 32 columns
        #pragma unroll
        for (int off = 4; off > 0; off >>= 1)
            partial += __shfl_xor_sync(0xffffffffu, partial, off, 8);

        if (q == 0)
            g_partial[(rbase + rl) * NSLICE + s] = partial;

        __syncthreads();   // protect staging buffers before next store
        it = itn;
    }
}

__global__ void out_kernel(const float* __restrict__ out_b, float* __restrict__ out)
{
    const int b = blockIdx.x * blockDim.x + threadIdx.x;
    if (b < BATCH) {
        const float4* gp = (const float4*)(g_partial + b * NSLICE);
        float x = out_b[0];
        #pragma unroll
        for (int i = 0; i < NSLICE / 4; i++) {
            const float4 p = gp[i];
            x += p.x + p.y + p.z + p.w;
        }
        out[b] = 1.0f / (1.0f + __expf(-x));
    }
}

extern "C" void kernel_launch(void* const* d_in, const int* in_sizes, int n_in,
                              void* d_out, int out_size)
{
    (void)in_sizes; (void)n_in; (void)out_size;
    const int*   stm_idx  = (const int*)  d_in[0];  // [2, NNZ] int32
    const int*   nstm_idx = (const int*)  d_in[1];  // [2, NNZ] int32
    const float* values   = (const float*)d_in[2];  // [NNZ]
    const float* ft_w     = (const float*)d_in[3];  // [768, 512]
    const float* ft_b     = (const float*)d_in[4];  // [512]
    const float* out_w    = (const float*)d_in[5];  // [1024, 1]
    const float* out_b    = (const float*)d_in[6];  // [1]
    float* out = (float*)d_out;

    cudaFuncSetAttribute(ft_kernel, cudaFuncAttributeMaxDynamicSharedMemorySize, SM_BYTES);

    dim3 grid(BLOCKS_X, NSLICE);
    ft_kernel<<<grid, THREADS, SM_BYTES>>>(stm_idx, nstm_idx, values, ft_w, ft_b, out_w);
    out_kernel<<<(BATCH + 255) / 256, 256>>>(out_b, out);
}